// round 14
// baseline (speedup 1.0000x reference)
#include <cuda_runtime.h>
#include <cuda_bf16.h>
#include <cstdint>

// ---------------- problem dims ----------------
#define MDIM 8192
#define KDIM 4096
#define NDIM 16384

// ---------------- GEMM tiling (bf16 HMMA) ----------------
#define BM 128
#define BN 256
#define BK 64                            // per sub-tile; stage = 2 sub-tiles (K=128)
#define STAGES 2
#define A_ST (BM * BK * 2)               // 16384 bytes (bf16)
#define B_ST (BN * BK * 2)               // 32768 bytes
#define STG_BYTES (2 * A_ST + 2 * B_ST)  // 98304 per stage (K=128)
#define SMEM_TILES 1024
#define SMEM_TOTAL (SMEM_TILES + STAGES * STG_BYTES)  // 197632
#define KTILES (KDIM / BK)               // 64 sub-tiles
#define KSTEPS (KTILES / 2)              // 32 stages consumed
#define NT_M (MDIM / BM)                 // 64
#define NT_N (NDIM / BN)                 // 64

// ---------------- device scratch (zero-initialized at module load) --------
// Pre-swizzled tile-major layouts (exact smem image for bulk copy):
//  A tile (mt,kt): 16384 B; row r(0..127), 16B chunk c(0..7) at
//                  r*128 + ((c ^ (r&7))<<4)
//  B tile (nt,kt): 32768 B; rows r(0..255), same swizzle.
__device__ float g_xmax[KDIM];
__device__ float g_wmax[KDIM];
__device__ float g_xs[MDIM];
__device__ float g_ws[NDIM];
__device__ __nv_bfloat16 g_xq[(size_t)MDIM * KDIM];  // 64 MB tile-major swizzled
__device__ __nv_bfloat16 g_wq[(size_t)NDIM * KDIM];  // 128 MB tile-major swizzled

// ---------------- PTX helpers ----------------
__device__ __forceinline__ uint32_t smem_u32(const void* p) {
    uint32_t a;
    asm("{ .reg .u64 t; cvta.to.shared.u64 t, %1; cvt.u32.u64 %0, t; }" : "=r"(a) : "l"(p));
    return a;
}

#define MBARRIER_INIT(a, c) \
    asm volatile("mbarrier.init.shared.b64 [%0], %1;" :: "r"(a), "r"((uint32_t)(c)) : "memory")
#define MBARRIER_EXPECT_TX(a, b) \
    asm volatile("mbarrier.arrive.expect_tx.shared.b64 _, [%0], %1;" \
        :: "r"(a), "r"((uint32_t)(b)) : "memory")
#define MBARRIER_ARRIVE(a) \
    asm volatile("mbarrier.arrive.shared.b64 _, [%0];" :: "r"(a) : "memory")

__device__ __forceinline__ void mbar_wait(uint32_t mbar, uint32_t parity) {
    asm volatile(
        "{\n\t"
        ".reg .pred P;\n\t"
        "W_%=:\n\t"
        "mbarrier.try_wait.parity.acquire.cta.shared::cta.b64 P, [%0], %1, 0x989680;\n\t"
        "@!P bra W_%=;\n\t"
        "}" :: "r"(mbar), "r"(parity) : "memory");
}

#define BULK_G2S(dst, src, nbytes, mbar) \
    asm volatile("cp.async.bulk.shared::cluster.global.mbarrier::complete_tx::bytes " \
        "[%0], [%1], %2, [%3];" \
        :: "r"(dst), "l"(src), "r"((uint32_t)(nbytes)), "r"(mbar) : "memory")

__device__ __forceinline__ void ldm_x4(uint32_t& r0, uint32_t& r1, uint32_t& r2, uint32_t& r3,
                                       uint32_t addr) {
    asm volatile("ldmatrix.sync.aligned.m8n8.x4.shared.b16 {%0,%1,%2,%3}, [%4];"
                 : "=r"(r0), "=r"(r1), "=r"(r2), "=r"(r3) : "r"(addr));
}

// bf16 HMMA m16n8k16, f32 accumulate
__device__ __forceinline__ void hmma16816(float* c, const uint32_t* a, uint32_t b0,
                                          uint32_t b1) {
    asm volatile(
        "mma.sync.aligned.m16n8k16.row.col.f32.bf16.bf16.f32 "
        "{%0,%1,%2,%3}, {%4,%5,%6,%7}, {%8,%9}, {%0,%1,%2,%3};"
        : "+f"(c[0]), "+f"(c[1]), "+f"(c[2]), "+f"(c[3])
        : "r"(a[0]), "r"(a[1]), "r"(a[2]), "r"(a[3]), "r"(b0), "r"(b1));
}

// ---------------- exact pow2-ceil scale (matches jnp.exp2(ceil(log2(s)))) ----
__device__ __forceinline__ float pow2_scale(float amax) {
    float s = fmaxf(amax / 127.0f, 1e-30f);
    int e;
    float f = frexpf(s, &e);  // s = f * 2^e, f in [0.5, 1)
    return ldexpf(1.0f, (f == 0.5f) ? (e - 1) : e);
}

// ---------------- kernel: column absmax for BOTH x and w (one launch) -----
// 256 rows per block (4 independent max chains per thread, float4 loads).
__global__ void k_colmax_all(const float* __restrict__ x, const float* __restrict__ w) {
    int c4 = blockIdx.x * blockDim.x + threadIdx.x;  // float4 column index
    int ybl = blockIdx.y;
    const float* src;
    float* dst;
    if (ybl < MDIM / 256) {
        src = x + (size_t)(ybl * 256) * KDIM;
        dst = g_xmax;
    } else {
        src = w + (size_t)((ybl - MDIM / 256) * 256) * KDIM;
        dst = g_wmax;
    }
    const float4* p = (const float4*)src + c4;
    float mx = 0.0f, my = 0.0f, mz = 0.0f, mw = 0.0f;
#pragma unroll 4
    for (int r = 0; r < 256; r++) {
        float4 v = p[(size_t)r * (KDIM / 4)];
        mx = fmaxf(mx, fabsf(v.x));
        my = fmaxf(my, fabsf(v.y));
        mz = fmaxf(mz, fabsf(v.z));
        mw = fmaxf(mw, fabsf(v.w));
    }
    atomicMax((int*)&dst[c4 * 4 + 0], __float_as_int(mx));
    atomicMax((int*)&dst[c4 * 4 + 1], __float_as_int(my));
    atomicMax((int*)&dst[c4 * 4 + 2], __float_as_int(mz));
    atomicMax((int*)&dst[c4 * 4 + 3], __float_as_int(mw));
}

// ---------------- block max reduce (256 threads) ----------------
__device__ __forceinline__ float block_amax(float v, float* sred) {
    int t = threadIdx.x;
#pragma unroll
    for (int o = 16; o; o >>= 1) v = fmaxf(v, __shfl_xor_sync(0xffffffffu, v, o));
    if ((t & 31) == 0) sred[t >> 5] = v;
    __syncthreads();
    if (t == 0) {
        float m = sred[0];
#pragma unroll
        for (int i = 1; i < 8; i++) m = fmaxf(m, sred[i]);
        sred[0] = m;
    }
    __syncthreads();
    return sred[0];
}

__device__ __forceinline__ float q8f(float v, float inv) {
    float q = rintf(v * inv);
    return fminf(fmaxf(q, -127.0f), 127.0f);
}

// pack 8 quantized floats -> uint4 of bf16
__device__ __forceinline__ uint4 pack8(const float* v, float inv) {
    uint4 u;
    __nv_bfloat162 p0 = __floats2bfloat162_rn(q8f(v[0], inv), q8f(v[1], inv));
    __nv_bfloat162 p1 = __floats2bfloat162_rn(q8f(v[2], inv), q8f(v[3], inv));
    __nv_bfloat162 p2 = __floats2bfloat162_rn(q8f(v[4], inv), q8f(v[5], inv));
    __nv_bfloat162 p3 = __floats2bfloat162_rn(q8f(v[6], inv), q8f(v[7], inv));
    u.x = *(uint32_t*)&p0; u.y = *(uint32_t*)&p1;
    u.z = *(uint32_t*)&p2; u.w = *(uint32_t*)&p3;
    return u;
}

// ---------------- kernel: quantize X AND W -> swizzled bf16 tiles ---------
// one block = one row. blockIdx.x < MDIM -> X row (divide by smooth);
// else W row (multiply by smooth). smooth = sqrt(xmax*wmax) inline.
__global__ void k_quant_all(const float* __restrict__ x, const float* __restrict__ w) {
    __shared__ float sred[8];
    int bid = blockIdx.x;
    int t = threadIdx.x;
    bool isX = bid < MDIM;
    int row = isX ? bid : bid - MDIM;
    const float* src = isX ? (x + (size_t)row * KDIM) : (w + (size_t)row * KDIM);

    float v[16];
    float am = 0.0f;
#pragma unroll
    for (int g = 0; g < 2; g++) {
        int k = g * 2048 + t * 8;
#pragma unroll
        for (int j = 0; j < 8; j += 4) {
            float4 a = *(const float4*)(src + k + j);
            float4 xm = *(const float4*)(g_xmax + k + j);
            float4 wm = *(const float4*)(g_wmax + k + j);
            float* dv = v + g * 8 + j;
            float s0 = sqrtf(xm.x * wm.x), s1 = sqrtf(xm.y * wm.y);
            float s2 = sqrtf(xm.z * wm.z), s3 = sqrtf(xm.w * wm.w);
            if (isX) {
                dv[0] = a.x / s0; dv[1] = a.y / s1; dv[2] = a.z / s2; dv[3] = a.w / s3;
            } else {
                dv[0] = a.x * s0; dv[1] = a.y * s1; dv[2] = a.z * s2; dv[3] = a.w * s3;
            }
            am = fmaxf(am, fmaxf(fmaxf(fabsf(dv[0]), fabsf(dv[1])),
                                 fmaxf(fabsf(dv[2]), fabsf(dv[3]))));
        }
    }
    float scale = pow2_scale(block_amax(am, sred));
    if (t == 0) {
        if (isX) g_xs[row] = scale;
        else g_ws[row] = scale;
    }
    float inv = 1.0f / scale;  // exact (power of two)

    char* base;
    uint32_t rofs, sw;
    size_t tile_stride;
    if (isX) {
        int mt = row >> 7, r = row & 127;
        base = (char*)g_xq + (size_t)mt * KTILES * A_ST;
        rofs = (uint32_t)(r * 128);
        sw = (uint32_t)(r & 7);
        tile_stride = A_ST;
    } else {
        int nt = row >> 8, r = row & 255;
        base = (char*)g_wq + (size_t)nt * KTILES * B_ST;
        rofs = (uint32_t)(r * 128);
        sw = (uint32_t)(r & 7);
        tile_stride = B_ST;
    }
#pragma unroll
    for (int g = 0; g < 2; g++) {
        int k = g * 2048 + t * 8;
        int kt = k >> 6;
        uint32_t c = (uint32_t)((k >> 3) & 7);
        uint4 u = pack8(v + g * 8, inv);
        *(uint4*)(base + (size_t)kt * tile_stride + rofs + ((c ^ sw) << 4)) = u;
    }
}

// ---------------- GEMM: bf16 HMMA, 2-stage K=128 pipeline, rotating -------
// producer. 256 threads = 8 warps (2m x 4n), warp tile 64x64, CTA 128x256.
// Stage c is produced by lane 0 of warp (c & 7): no warp is systematically
// the straggler (vs. warp 0 paying the EMPTY-wait + TMA-issue every stage).
__global__ void __launch_bounds__(256, 1) k_gemm(const float* __restrict__ bias,
                                                 float* __restrict__ out) {
    extern __shared__ char smem[];
    uint32_t sb = smem_u32(smem);
    int tid = threadIdx.x;
    int wid = tid >> 5, lane = tid & 31;
    int wm = wid & 1, wn = wid >> 1;

#define FULLB(s) (sb + 16 + 8 * (s))
#define EMPTYB(s) (sb + 64 + 8 * (s))
    if (tid == 0) {
#pragma unroll
        for (int s = 0; s < STAGES; s++) {
            MBARRIER_INIT(FULLB(s), 1);
            MBARRIER_INIT(EMPTYB(s), 8);  // one arrive per warp (lane 0)
        }
    }
    __syncthreads();

    // tile rasterization: groups of 8 m-tiles
    int bid = blockIdx.x;
    int group = bid / (8 * NT_N);
    int rem = bid % (8 * NT_N);
    int mt = group * 8 + (rem & 7);
    int nt = rem >> 3;

    const char* Ab = (const char*)g_xq + (size_t)mt * KTILES * A_ST;
    const char* Bb = (const char*)g_wq + (size_t)nt * KTILES * B_ST;

    auto produce = [&](int c) {  // c in [0, KSTEPS)
        int s = c & 1;
        int p = c >> 1;
        mbar_wait(EMPTYB(s), (uint32_t)((p & 1) ^ 1));
        MBARRIER_EXPECT_TX(FULLB(s), STG_BYTES);
        uint32_t st = sb + SMEM_TILES + s * STG_BYTES;
        BULK_G2S(st, Ab + (size_t)c * 2 * A_ST, 2 * A_ST, FULLB(s));
        BULK_G2S(st + 2 * A_ST, Bb + (size_t)c * 2 * B_ST, 2 * B_ST, FULLB(s));
    };

    if (tid == 0) produce(0);

    float acc[4][8][4];
#pragma unroll
    for (int a = 0; a < 4; a++)
#pragma unroll
        for (int b = 0; b < 8; b++)
#pragma unroll
            for (int c = 0; c < 4; c++) acc[a][b][c] = 0.0f;

    int lrow = lane & 15;
    int lhi = lane >> 4;
    uint32_t aRow = (uint32_t)(wm * 64 + lrow);
    uint32_t bRow = (uint32_t)(wn * 64 + lrow);
    uint32_t swA = aRow & 7, swB = bRow & 7;

    for (int kt2 = 0; kt2 < KSTEPS; kt2++) {
        // rotating producer: stage kt2+1 produced by warp ((kt2+1) & 7)
        int cnext = kt2 + 1;
        if (cnext < KSTEPS && lane == 0 && wid == (cnext & 7)) produce(cnext);

        int s = kt2 & 1;
        mbar_wait(FULLB(s), (uint32_t)((kt2 >> 1) & 1));

        uint32_t stage = sb + SMEM_TILES + s * STG_BYTES;

#pragma unroll
        for (int half = 0; half < 2; half++) {
            uint32_t As = stage + half * A_ST;
            uint32_t Bs = stage + 2 * A_ST + half * B_ST;
#pragma unroll
            for (int ks = 0; ks < 4; ks++) {  // 4 x k16 per BK=64 sub-tile
                uint32_t cc = (uint32_t)(ks * 2 + lhi);
                uint32_t ca = (cc ^ swA) << 4, cb = (cc ^ swB) << 4;
                uint32_t a[4][4];
#pragma unroll
                for (int mf = 0; mf < 4; mf++) {
                    uint32_t addr = As + (aRow + mf * 16) * 128 + ca;
                    ldm_x4(a[mf][0], a[mf][1], a[mf][2], a[mf][3], addr);
                }
                uint32_t b0[8], b1[8];
#pragma unroll
                for (int j = 0; j < 4; j++) {
                    uint32_t t0, t1, t2, t3;
                    uint32_t addr = Bs + (bRow + j * 16) * 128 + cb;
                    ldm_x4(t0, t1, t2, t3, addr);
                    b0[2 * j] = t0; b1[2 * j] = t2;
                    b0[2 * j + 1] = t1; b1[2 * j + 1] = t3;
                }
#pragma unroll
                for (int mf = 0; mf < 4; mf++)
#pragma unroll
                    for (int nf = 0; nf < 8; nf++)
                        hmma16816(acc[mf][nf], a[mf], b0[nf], b1[nf]);
            }
        }
        if (lane == 0) MBARRIER_ARRIVE(EMPTYB(s));
    }

    // epilogue: out = acc * xs[m] * ws[n] + bias[n]
    int mbase = mt * BM + wm * 64 + (lane >> 2);
    int nbase = nt * BN + wn * 64 + (lane & 3) * 2;
#pragma unroll
    for (int mf = 0; mf < 4; mf++) {
        int m0 = mbase + mf * 16;
        int m1 = m0 + 8;
        float xs0 = g_xs[m0], xs1 = g_xs[m1];
        float* o0 = out + (size_t)m0 * NDIM;
        float* o1 = out + (size_t)m1 * NDIM;
#pragma unroll
        for (int nf = 0; nf < 8; nf++) {
            int n = nbase + nf * 8;
            float ws0 = g_ws[n], ws1 = g_ws[n + 1];
            float bb0 = bias[n], bb1 = bias[n + 1];
            float2 r0, r1;
            r0.x = acc[mf][nf][0] * xs0 * ws0 + bb0;
            r0.y = acc[mf][nf][1] * xs0 * ws1 + bb1;
            r1.x = acc[mf][nf][2] * xs1 * ws0 + bb0;
            r1.y = acc[mf][nf][3] * xs1 * ws1 + bb1;
            *(float2*)(o0 + n) = r0;
            *(float2*)(o1 + n) = r1;
        }
    }
}

// ---------------- launch (3 launches; GEMM = launch index 2) --------------
extern "C" void kernel_launch(void* const* d_in, const int* in_sizes, int n_in,
                              void* d_out, int out_size) {
    const float* x = (const float*)d_in[0];     // [M, K]
    const float* w = (const float*)d_in[1];     // [N, K]
    const float* bias = (const float*)d_in[2];  // [N]
    float* out = (float*)d_out;                 // [M, N]

    k_colmax_all<<<dim3(KDIM / 1024, (MDIM + NDIM) / 256), 256>>>(x, w);
    k_quant_all<<<MDIM + NDIM, 256>>>(x, w);

    cudaFuncSetAttribute(k_gemm, cudaFuncAttributeMaxDynamicSharedMemorySize, SMEM_TOTAL);
    k_gemm<<<NT_M * NT_N, 256, SMEM_TOTAL>>>(bias, out);
}

// round 15
// speedup vs baseline: 1.0194x; 1.0194x over previous
#include <cuda_runtime.h>
#include <cuda_bf16.h>
#include <cstdint>

// ---------------- problem dims ----------------
#define MDIM 8192
#define KDIM 4096
#define NDIM 16384

// ---------------- GEMM tiling (bf16 HMMA) ----------------
#define BM 128
#define BN 256
#define BK 64                            // per sub-tile; stage = 2 sub-tiles (K=128)
#define STAGES 2
#define A_ST (BM * BK * 2)               // 16384 bytes (bf16)
#define B_ST (BN * BK * 2)               // 32768 bytes
#define STG_BYTES (2 * A_ST + 2 * B_ST)  // 98304 per stage (K=128)
#define SMEM_TILES 1024
#define SMEM_TOTAL (SMEM_TILES + STAGES * STG_BYTES)  // 197632
#define KTILES (KDIM / BK)               // 64 sub-tiles
#define KSTEPS (KTILES / 2)              // 32 stages consumed
#define NT_M (MDIM / BM)                 // 64
#define NT_N (NDIM / BN)                 // 64

// ---------------- device scratch (zero-initialized at module load) --------
// Pre-swizzled tile-major layouts (exact smem image for bulk copy):
//  A tile (mt,kt): 16384 B; row r(0..127), 16B chunk c(0..7) at
//                  r*128 + ((c ^ (r&7))<<4)
//  B tile (nt,kt): 32768 B; rows r(0..255), same swizzle.
__device__ float g_xmax[KDIM];
__device__ float g_wmax[KDIM];
__device__ float g_smooth[KDIM];
__device__ float g_xs[MDIM];
__device__ float g_ws[NDIM];
__device__ __nv_bfloat16 g_xq[(size_t)MDIM * KDIM];  // 64 MB tile-major swizzled
__device__ __nv_bfloat16 g_wq[(size_t)NDIM * KDIM];  // 128 MB tile-major swizzled

// ---------------- PTX helpers ----------------
__device__ __forceinline__ uint32_t smem_u32(const void* p) {
    uint32_t a;
    asm("{ .reg .u64 t; cvta.to.shared.u64 t, %1; cvt.u32.u64 %0, t; }" : "=r"(a) : "l"(p));
    return a;
}

#define MBARRIER_INIT(a, c) \
    asm volatile("mbarrier.init.shared.b64 [%0], %1;" :: "r"(a), "r"((uint32_t)(c)) : "memory")
#define MBARRIER_EXPECT_TX(a, b) \
    asm volatile("mbarrier.arrive.expect_tx.shared.b64 _, [%0], %1;" \
        :: "r"(a), "r"((uint32_t)(b)) : "memory")
#define MBARRIER_ARRIVE(a) \
    asm volatile("mbarrier.arrive.shared.b64 _, [%0];" :: "r"(a) : "memory")

__device__ __forceinline__ void mbar_wait(uint32_t mbar, uint32_t parity) {
    asm volatile(
        "{\n\t"
        ".reg .pred P;\n\t"
        "W_%=:\n\t"
        "mbarrier.try_wait.parity.acquire.cta.shared::cta.b64 P, [%0], %1, 0x989680;\n\t"
        "@!P bra W_%=;\n\t"
        "}" :: "r"(mbar), "r"(parity) : "memory");
}

#define BULK_G2S(dst, src, nbytes, mbar) \
    asm volatile("cp.async.bulk.shared::cluster.global.mbarrier::complete_tx::bytes " \
        "[%0], [%1], %2, [%3];" \
        :: "r"(dst), "l"(src), "r"((uint32_t)(nbytes)), "r"(mbar) : "memory")

__device__ __forceinline__ void ldm_x4(uint32_t& r0, uint32_t& r1, uint32_t& r2, uint32_t& r3,
                                       uint32_t addr) {
    asm volatile("ldmatrix.sync.aligned.m8n8.x4.shared.b16 {%0,%1,%2,%3}, [%4];"
                 : "=r"(r0), "=r"(r1), "=r"(r2), "=r"(r3) : "r"(addr));
}

// bf16 HMMA m16n8k16, f32 accumulate
__device__ __forceinline__ void hmma16816(float* c, const uint32_t* a, uint32_t b0,
                                          uint32_t b1) {
    asm volatile(
        "mma.sync.aligned.m16n8k16.row.col.f32.bf16.bf16.f32 "
        "{%0,%1,%2,%3}, {%4,%5,%6,%7}, {%8,%9}, {%0,%1,%2,%3};"
        : "+f"(c[0]), "+f"(c[1]), "+f"(c[2]), "+f"(c[3])
        : "r"(a[0]), "r"(a[1]), "r"(a[2]), "r"(a[3]), "r"(b0), "r"(b1));
}

// ---------------- exact pow2-ceil scale (matches jnp.exp2(ceil(log2(s)))) ----
__device__ __forceinline__ float pow2_scale(float amax) {
    float s = fmaxf(amax / 127.0f, 1e-30f);
    int e;
    float f = frexpf(s, &e);  // s = f * 2^e, f in [0.5, 1)
    return ldexpf(1.0f, (f == 0.5f) ? (e - 1) : e);
}

// ---------------- kernel: column absmax for BOTH x and w (one launch) -----
// 128 rows per block (4 independent max chains per thread, float4 loads).
__global__ void k_colmax_all(const float* __restrict__ x, const float* __restrict__ w) {
    int c4 = blockIdx.x * blockDim.x + threadIdx.x;  // float4 column index
    int ybl = blockIdx.y;
    const float* src;
    float* dst;
    if (ybl < MDIM / 128) {
        src = x + (size_t)(ybl * 128) * KDIM;
        dst = g_xmax;
    } else {
        src = w + (size_t)((ybl - MDIM / 128) * 128) * KDIM;
        dst = g_wmax;
    }
    const float4* p = (const float4*)src + c4;
    float mx = 0.0f, my = 0.0f, mz = 0.0f, mw = 0.0f;
#pragma unroll 4
    for (int r = 0; r < 128; r++) {
        float4 v = p[(size_t)r * (KDIM / 4)];
        mx = fmaxf(mx, fabsf(v.x));
        my = fmaxf(my, fabsf(v.y));
        mz = fmaxf(mz, fabsf(v.z));
        mw = fmaxf(mw, fabsf(v.w));
    }
    atomicMax((int*)&dst[c4 * 4 + 0], __float_as_int(mx));
    atomicMax((int*)&dst[c4 * 4 + 1], __float_as_int(my));
    atomicMax((int*)&dst[c4 * 4 + 2], __float_as_int(mz));
    atomicMax((int*)&dst[c4 * 4 + 3], __float_as_int(mw));
}

// ---------------- kernel: smooth scale (once per column) ----------------
__global__ void k_smooth() {
    int k = blockIdx.x * blockDim.x + threadIdx.x;
    if (k < KDIM) g_smooth[k] = sqrtf(g_xmax[k] * g_wmax[k]);
}

// ---------------- block max reduce (256 threads) ----------------
__device__ __forceinline__ float block_amax(float v, float* sred) {
    int t = threadIdx.x;
#pragma unroll
    for (int o = 16; o; o >>= 1) v = fmaxf(v, __shfl_xor_sync(0xffffffffu, v, o));
    if ((t & 31) == 0) sred[t >> 5] = v;
    __syncthreads();
    if (t == 0) {
        float m = sred[0];
#pragma unroll
        for (int i = 1; i < 8; i++) m = fmaxf(m, sred[i]);
        sred[0] = m;
    }
    __syncthreads();
    return sred[0];
}

__device__ __forceinline__ float q8f(float v, float inv) {
    float q = rintf(v * inv);
    return fminf(fmaxf(q, -127.0f), 127.0f);
}

// pack 8 quantized floats -> uint4 of bf16
__device__ __forceinline__ uint4 pack8(const float* v, float inv) {
    uint4 u;
    __nv_bfloat162 p0 = __floats2bfloat162_rn(q8f(v[0], inv), q8f(v[1], inv));
    __nv_bfloat162 p1 = __floats2bfloat162_rn(q8f(v[2], inv), q8f(v[3], inv));
    __nv_bfloat162 p2 = __floats2bfloat162_rn(q8f(v[4], inv), q8f(v[5], inv));
    __nv_bfloat162 p3 = __floats2bfloat162_rn(q8f(v[6], inv), q8f(v[7], inv));
    u.x = *(uint32_t*)&p0; u.y = *(uint32_t*)&p1;
    u.z = *(uint32_t*)&p2; u.w = *(uint32_t*)&p3;
    return u;
}

// ---------------- kernel: quantize X AND W -> swizzled bf16 tiles ---------
// one block = one row. blockIdx.x < MDIM -> X row (divide by smooth);
// else W row (multiply by smooth). smooth precomputed by k_smooth.
__global__ void k_quant_all(const float* __restrict__ x, const float* __restrict__ w) {
    __shared__ float sred[8];
    int bid = blockIdx.x;
    int t = threadIdx.x;
    bool isX = bid < MDIM;
    int row = isX ? bid : bid - MDIM;
    const float* src = isX ? (x + (size_t)row * KDIM) : (w + (size_t)row * KDIM);

    float v[16];
    float am = 0.0f;
#pragma unroll
    for (int g = 0; g < 2; g++) {
        int k = g * 2048 + t * 8;
#pragma unroll
        for (int j = 0; j < 8; j += 4) {
            float4 a = *(const float4*)(src + k + j);
            float4 s = *(const float4*)(g_smooth + k + j);
            float* dv = v + g * 8 + j;
            if (isX) {
                dv[0] = a.x / s.x; dv[1] = a.y / s.y;
                dv[2] = a.z / s.z; dv[3] = a.w / s.w;
            } else {
                dv[0] = a.x * s.x; dv[1] = a.y * s.y;
                dv[2] = a.z * s.z; dv[3] = a.w * s.w;
            }
            am = fmaxf(am, fmaxf(fmaxf(fabsf(dv[0]), fabsf(dv[1])),
                                 fmaxf(fabsf(dv[2]), fabsf(dv[3]))));
        }
    }
    float scale = pow2_scale(block_amax(am, sred));
    if (t == 0) {
        if (isX) g_xs[row] = scale;
        else g_ws[row] = scale;
    }
    float inv = 1.0f / scale;  // exact (power of two)

    char* base;
    uint32_t rofs, sw;
    size_t tile_stride;
    if (isX) {
        int mt = row >> 7, r = row & 127;
        base = (char*)g_xq + (size_t)mt * KTILES * A_ST;
        rofs = (uint32_t)(r * 128);
        sw = (uint32_t)(r & 7);
        tile_stride = A_ST;
    } else {
        int nt = row >> 8, r = row & 255;
        base = (char*)g_wq + (size_t)nt * KTILES * B_ST;
        rofs = (uint32_t)(r * 128);
        sw = (uint32_t)(r & 7);
        tile_stride = B_ST;
    }
#pragma unroll
    for (int g = 0; g < 2; g++) {
        int k = g * 2048 + t * 8;
        int kt = k >> 6;
        uint32_t c = (uint32_t)((k >> 3) & 7);
        uint4 u = pack8(v + g * 8, inv);
        *(uint4*)(base + (size_t)kt * tile_stride + rofs + ((c ^ sw) << 4)) = u;
    }
}

// ---------------- GEMM: bf16 HMMA + bulk-copy 2-stage deep pipeline -------
// (round-10/13 kernel, verbatim: best known — tensor 74.5%)
// 256 threads = 8 warps (2m x 4n), warp tile 64x64, CTA 128x256, K=128/stage.
__global__ void __launch_bounds__(256, 1) k_gemm(const float* __restrict__ bias,
                                                 float* __restrict__ out) {
    extern __shared__ char smem[];
    uint32_t sb = smem_u32(smem);
    int tid = threadIdx.x;
    int wid = tid >> 5, lane = tid & 31;
    int wm = wid & 1, wn = wid >> 1;

#define FULLB(s) (sb + 16 + 8 * (s))
#define EMPTYB(s) (sb + 64 + 8 * (s))
    if (tid == 0) {
#pragma unroll
        for (int s = 0; s < STAGES; s++) {
            MBARRIER_INIT(FULLB(s), 1);
            MBARRIER_INIT(EMPTYB(s), 8);  // one arrive per warp (lane 0)
        }
    }
    __syncthreads();

    // tile rasterization: groups of 8 m-tiles
    int bid = blockIdx.x;
    int group = bid / (8 * NT_N);
    int rem = bid % (8 * NT_N);
    int mt = group * 8 + (rem & 7);
    int nt = rem >> 3;

    const char* Ab = (const char*)g_xq + (size_t)mt * KTILES * A_ST;
    const char* Bb = (const char*)g_wq + (size_t)nt * KTILES * B_ST;

    auto produce = [&](int c) {  // c in [0, KSTEPS)
        int s = c & 1;
        int p = c >> 1;
        mbar_wait(EMPTYB(s), (uint32_t)((p & 1) ^ 1));
        MBARRIER_EXPECT_TX(FULLB(s), STG_BYTES);
        uint32_t st = sb + SMEM_TILES + s * STG_BYTES;
        BULK_G2S(st, Ab + (size_t)c * 2 * A_ST, 2 * A_ST, FULLB(s));
        BULK_G2S(st + 2 * A_ST, Bb + (size_t)c * 2 * B_ST, 2 * B_ST, FULLB(s));
    };

    if (tid == 0) produce(0);

    float acc[4][8][4];
#pragma unroll
    for (int a = 0; a < 4; a++)
#pragma unroll
        for (int b = 0; b < 8; b++)
#pragma unroll
            for (int c = 0; c < 4; c++) acc[a][b][c] = 0.0f;

    int lrow = lane & 15;
    int lhi = lane >> 4;
    uint32_t aRow = (uint32_t)(wm * 64 + lrow);
    uint32_t bRow = (uint32_t)(wn * 64 + lrow);
    uint32_t swA = aRow & 7, swB = bRow & 7;

    for (int kt2 = 0; kt2 < KSTEPS; kt2++) {
        if (tid == 0 && kt2 + 1 < KSTEPS) produce(kt2 + 1);

        int s = kt2 & 1;
        mbar_wait(FULLB(s), (uint32_t)((kt2 >> 1) & 1));

        uint32_t stage = sb + SMEM_TILES + s * STG_BYTES;

#pragma unroll
        for (int half = 0; half < 2; half++) {
            uint32_t As = stage + half * A_ST;
            uint32_t Bs = stage + 2 * A_ST + half * B_ST;
#pragma unroll
            for (int ks = 0; ks < 4; ks++) {  // 4 x k16 per BK=64 sub-tile
                uint32_t cc = (uint32_t)(ks * 2 + lhi);
                uint32_t ca = (cc ^ swA) << 4, cb = (cc ^ swB) << 4;
                uint32_t a[4][4];
#pragma unroll
                for (int mf = 0; mf < 4; mf++) {
                    uint32_t addr = As + (aRow + mf * 16) * 128 + ca;
                    ldm_x4(a[mf][0], a[mf][1], a[mf][2], a[mf][3], addr);
                }
                uint32_t b0[8], b1[8];
#pragma unroll
                for (int j = 0; j < 4; j++) {
                    uint32_t t0, t1, t2, t3;
                    uint32_t addr = Bs + (bRow + j * 16) * 128 + cb;
                    ldm_x4(t0, t1, t2, t3, addr);
                    b0[2 * j] = t0; b1[2 * j] = t2;
                    b0[2 * j + 1] = t1; b1[2 * j + 1] = t3;
                }
#pragma unroll
                for (int mf = 0; mf < 4; mf++)
#pragma unroll
                    for (int nf = 0; nf < 8; nf++)
                        hmma16816(acc[mf][nf], a[mf], b0[nf], b1[nf]);
            }
        }
        if (lane == 0) MBARRIER_ARRIVE(EMPTYB(s));
    }

    // epilogue: out = acc * xs[m] * ws[n] + bias[n]
    int mbase = mt * BM + wm * 64 + (lane >> 2);
    int nbase = nt * BN + wn * 64 + (lane & 3) * 2;
#pragma unroll
    for (int mf = 0; mf < 4; mf++) {
        int m0 = mbase + mf * 16;
        int m1 = m0 + 8;
        float xs0 = g_xs[m0], xs1 = g_xs[m1];
        float* o0 = out + (size_t)m0 * NDIM;
        float* o1 = out + (size_t)m1 * NDIM;
#pragma unroll
        for (int nf = 0; nf < 8; nf++) {
            int n = nbase + nf * 8;
            float ws0 = g_ws[n], ws1 = g_ws[n + 1];
            float bb0 = bias[n], bb1 = bias[n + 1];
            float2 r0, r1;
            r0.x = acc[mf][nf][0] * xs0 * ws0 + bb0;
            r0.y = acc[mf][nf][1] * xs0 * ws1 + bb1;
            r1.x = acc[mf][nf][2] * xs1 * ws0 + bb0;
            r1.y = acc[mf][nf][3] * xs1 * ws1 + bb1;
            *(float2*)(o0 + n) = r0;
            *(float2*)(o1 + n) = r1;
        }
    }
}

// ---------------- launch (4 launches; GEMM = launch index 3) --------------
extern "C" void kernel_launch(void* const* d_in, const int* in_sizes, int n_in,
                              void* d_out, int out_size) {
    const float* x = (const float*)d_in[0];     // [M, K]
    const float* w = (const float*)d_in[1];     // [N, K]
    const float* bias = (const float*)d_in[2];  // [N]
    float* out = (float*)d_out;                 // [M, N]

    k_colmax_all<<<dim3(KDIM / 1024, (MDIM + NDIM) / 128), 256>>>(x, w);
    k_smooth<<<KDIM / 256, 256>>>();
    k_quant_all<<<MDIM + NDIM, 256>>>(x, w);

    cudaFuncSetAttribute(k_gemm, cudaFuncAttributeMaxDynamicSharedMemorySize, SMEM_TOTAL);
    k_gemm<<<NT_M * NT_N, 256, SMEM_TOTAL>>>(bias, out);
}